// round 3
// baseline (speedup 1.0000x reference)
#include <cuda_runtime.h>

// Second-order conv2d: out[b,o,h,w] = sum_{c,f} phi_f(3x3 patch of x[b,c] at (h,w)) * w[o,c,f]
// phi: 9 linear taps, 9 squares, 36 cross products (PM_cross ordering).
// Implemented as fused implicit SGEMM, M=128(oc) x N=73728(b*h*w) x K=3456(c*54),
// with Blackwell packed f32x2 FMA (FFMA2) accumulators.

#define NB 8
#define NC 64
#define NOC 128
#define NF 54
#define IH 96
#define IW 96
#define TILE_H 8
#define TILE_W 16
#define NTW (IW / TILE_W)            // 6
#define NTH (IH / TILE_H)            // 12
#define TILES_PER_IMG (NTW * NTH)    // 72

// Pre-transposed weights: [c][f][o], filled by transpose_w_kernel each launch.
__device__ __align__(16) float g_wT[NC * NF * NOC];

__global__ void transpose_w_kernel(const float* __restrict__ w) {
    int idx = blockIdx.x * blockDim.x + threadIdx.x;
    if (idx < NOC * NC * NF) {
        int f = idx % NF;
        int t = idx / NF;
        int c = t % NC;
        int o = t / NC;
        // w layout: [o][c][f][1] row-major
        g_wT[(c * NF + f) * NOC + o] = w[idx];
    }
}

__device__ __forceinline__ unsigned long long pack_dup(float v) {
    unsigned long long r;
    asm("mov.b64 %0, {%1, %1};" : "=l"(r) : "f"(v));
    return r;
}

__device__ __forceinline__ void ffma2(unsigned long long& d,
                                      unsigned long long a,
                                      unsigned long long b) {
    // packed f32x2 fused multiply-add: d = a * b + d (elementwise on 2 floats)
    asm("fma.rn.f32x2 %0, %1, %2, %0;" : "+l"(d) : "l"(a), "l"(b));
}

// SMEM layout (floats): [0,180) input halo tile (padded to 192),
// [192, 192+6912) weights [54][128], [7104, 7104+6912) features [54][128].
#define SMEM_FLOATS (192 + NF * NOC + NF * NOC)   // 14016
#define SMEM_BYTES  (SMEM_FLOATS * 4)             // 56064

__global__ void __launch_bounds__(256, 2)
soc_main_kernel(const float* __restrict__ x, float* __restrict__ out) {
    extern __shared__ float sm[];
    float* sIn = sm;           // 10*18 halo tile
    float* sW  = sm + 192;     // [f][oc]
    float* sF  = sm + 7104;    // [f][pos]

    const int tid = threadIdx.x;
    const int bx  = blockIdx.x;
    const int b   = bx / TILES_PER_IMG;
    const int t   = bx - b * TILES_PER_IMG;
    const int th  = t / NTW;
    const int h0  = th * TILE_H;
    const int w0  = (t - th * NTW) * TILE_W;

    const float* xb = x + (size_t)b * NC * IH * IW;

    const int ty  = tid >> 4;    // 0..15 -> oc group
    const int tx  = tid & 15;    // 0..15 -> position group
    const int oc0 = ty * 8;
    const int px0 = tx * 8;

    unsigned long long acc[8][4];
#pragma unroll
    for (int i = 0; i < 8; ++i)
#pragma unroll
        for (int j = 0; j < 4; ++j) acc[i][j] = 0ULL;

    const int pos = tid & 127;   // feature-gen position (both thread halves)
    const int pr  = pos >> 4;    // row in tile 0..7
    const int pc  = pos & 15;    // col in tile 0..15

    for (int c = 0; c < NC; ++c) {
        __syncthreads();  // previous iteration's consumers done

        // ---- load input halo tile (10 x 18, zero-padded at image borders) ----
        if (tid < 180) {
            int r  = tid / 18;
            int cc = tid - r * 18;
            int gh = h0 - 1 + r;
            int gw = w0 - 1 + cc;
            float v = 0.0f;
            if ((unsigned)gh < IH && (unsigned)gw < IW)
                v = xb[(size_t)c * IH * IW + gh * IW + gw];
            sIn[tid] = v;
        }
        // ---- load transposed weights for this channel: [54][128] contiguous ----
        {
            const float4* src = (const float4*)(g_wT + (size_t)c * NF * NOC);
            float4* dst = (float4*)sW;
#pragma unroll
            for (int i = 0; i < 7; ++i) {
                int k = tid + i * 256;
                if (k < (NF * NOC) / 4) dst[k] = src[k];
            }
        }
        __syncthreads();

        // ---- build 54 features per position into sF ----
        {
            float p[9];
#pragma unroll
            for (int kh = 0; kh < 3; ++kh)
#pragma unroll
                for (int kw = 0; kw < 3; ++kw)
                    p[kh * 3 + kw] = sIn[(pr + kh) * 18 + pc + kw];

            if (tid < 128) {
#pragma unroll
                for (int i = 0; i < 9; ++i) {
                    sF[i * 128 + pos]       = p[i];
                    sF[(9 + i) * 128 + pos] = p[i] * p[i];
                }
            } else {
                // PM_cross(2, 9) ordering: for j=1..8, pairs (i, i+j)
                const int I0[36] = {0,1,2,3,4,5,6,7, 0,1,2,3,4,5,6, 0,1,2,3,4,5,
                                    0,1,2,3,4, 0,1,2,3, 0,1,2, 0,1, 0};
                const int I1[36] = {1,2,3,4,5,6,7,8, 2,3,4,5,6,7,8, 3,4,5,6,7,8,
                                    4,5,6,7,8, 5,6,7,8, 6,7,8, 7,8, 8};
#pragma unroll
                for (int k = 0; k < 36; ++k)
                    sF[(18 + k) * 128 + pos] = p[I0[k]] * p[I1[k]];
            }
        }
        __syncthreads();

        // ---- main FMA loop: 8 oc x 8 pos per thread, f32x2 packed over pos pairs ----
#pragma unroll 1
        for (int f = 0; f < NF; ++f) {
            const float4* wr = (const float4*)(sW + f * 128 + oc0);
            float4 wa = wr[0];
            float4 wb = wr[1];
            const ulonglong2* fr = (const ulonglong2*)(sF + f * 128 + px0);
            ulonglong2 fA = fr[0];
            ulonglong2 fB = fr[1];

            unsigned long long wp[8];
            wp[0] = pack_dup(wa.x); wp[1] = pack_dup(wa.y);
            wp[2] = pack_dup(wa.z); wp[3] = pack_dup(wa.w);
            wp[4] = pack_dup(wb.x); wp[5] = pack_dup(wb.y);
            wp[6] = pack_dup(wb.z); wp[7] = pack_dup(wb.w);

#pragma unroll
            for (int i = 0; i < 8; ++i) {
                ffma2(acc[i][0], wp[i], fA.x);
                ffma2(acc[i][1], wp[i], fA.y);
                ffma2(acc[i][2], wp[i], fB.x);
                ffma2(acc[i][3], wp[i], fB.y);
            }
        }
    }

    // ---- epilogue: each thread owns 8 oc x 8 consecutive cols of one row ----
    const int row  = tx >> 1;
    const int col0 = (tx & 1) * 8;
    const int gh   = h0 + row;
    const int gw   = w0 + col0;
#pragma unroll
    for (int i = 0; i < 8; ++i) {
        float* op = out + (((size_t)(b * NOC + oc0 + i) * IH + gh) * IW + gw);
        float4 v0, v1;
        ((unsigned long long*)&v0)[0] = acc[i][0];
        ((unsigned long long*)&v0)[1] = acc[i][1];
        ((unsigned long long*)&v1)[0] = acc[i][2];
        ((unsigned long long*)&v1)[1] = acc[i][3];
        ((float4*)op)[0] = v0;
        ((float4*)op)[1] = v1;
    }
}

extern "C" void kernel_launch(void* const* d_in, const int* in_sizes, int n_in,
                              void* d_out, int out_size) {
    const float* x = (const float*)d_in[0];   // [8, 64, 96, 96] fp32
    const float* w = (const float*)d_in[1];   // [128, 64, 54, 1] fp32
    float* out = (float*)d_out;               // [8, 128, 96, 96] fp32

    (void)in_sizes; (void)n_in; (void)out_size;

    cudaFuncSetAttribute(soc_main_kernel,
                         cudaFuncAttributeMaxDynamicSharedMemorySize, SMEM_BYTES);

    transpose_w_kernel<<<(NOC * NC * NF + 255) / 256, 256>>>(w);
    soc_main_kernel<<<NB * TILES_PER_IMG, 256, SMEM_BYTES>>>(x, out);
}

// round 5
// speedup vs baseline: 1.9283x; 1.9283x over previous
#include <cuda_runtime.h>
#include <cuda_bf16.h>
#include <cstdint>

// Second-order conv2d as fused bf16-split implicit GEMM on mma.sync (HMMA).
// out[oc,pos] = sum_k W[oc,k] * F[k,pos]; K = 64 channels x 54 features (padded to 64).
// 3-term split: Wh*Fh + Wl*Fh + Wh*Fl, fp32 accumulate.

#define NB 8
#define NC 64
#define NOC 128
#define IH 96
#define IW 96
#define XCH (IH * IW)          // 9216
#define TILE_H 8
#define TILE_W 16
#define NTW 6
#define TILES_PER_IMG 72
#define KPAD 64                // K per channel padded 54 -> 64
#define WSTRIDE 72             // bf16 elems per oc row (144 B: 4-bank shift/row)
#define FSTRIDE 136            // bf16 elems per k row  (272 B: 4-bank shift/row)

// ---- SMEM layout (bytes) ----
#define SM_WH0 0
#define SM_WL0 18432
#define SM_WH1 36864
#define SM_WL1 55296
#define SM_FH0 73728
#define SM_FL0 91136
#define SM_FH1 108544
#define SM_FL1 125952
#define SM_TOTAL 143360

#define W_TILE_B 18432         // 128 * 72 * 2
#define W_CHUNKS (W_TILE_B / 16)  // 1152

// Pre-split, pre-padded weights: [ch][128 oc][72], cols 54..71 zero.
__device__ __align__(16) __nv_bfloat16 g_Wh[NC * NOC * WSTRIDE];
__device__ __align__(16) __nv_bfloat16 g_Wl[NC * NOC * WSTRIDE];

// ---------------- helpers ----------------
__device__ __forceinline__ uint32_t smem_u32(const void* p) {
    uint32_t a;
    asm("{ .reg .u64 t; cvta.to.shared.u64 t, %1; cvt.u32.u64 %0, t; }" : "=r"(a) : "l"(p));
    return a;
}

__device__ __forceinline__ void ldsm_x4(uint32_t* r, uint32_t addr) {
    asm volatile("ldmatrix.sync.aligned.m8n8.x4.shared.b16 {%0,%1,%2,%3}, [%4];"
                 : "=r"(r[0]), "=r"(r[1]), "=r"(r[2]), "=r"(r[3]) : "r"(addr));
}

__device__ __forceinline__ void ldsm_x2t(uint32_t* r, uint32_t addr) {
    asm volatile("ldmatrix.sync.aligned.m8n8.x2.trans.shared.b16 {%0,%1}, [%2];"
                 : "=r"(r[0]), "=r"(r[1]) : "r"(addr));
}

__device__ __forceinline__ void mma16816(float* d, const uint32_t* a, const uint32_t* b) {
    asm volatile(
        "mma.sync.aligned.m16n8k16.row.col.f32.bf16.bf16.f32 "
        "{%0,%1,%2,%3}, {%4,%5,%6,%7}, {%8,%9}, {%0,%1,%2,%3};"
        : "+f"(d[0]), "+f"(d[1]), "+f"(d[2]), "+f"(d[3])
        : "r"(a[0]), "r"(a[1]), "r"(a[2]), "r"(a[3]), "r"(b[0]), "r"(b[1]));
}

__device__ __forceinline__ void cpasync16(uint32_t dst, const void* src) {
    asm volatile("cp.async.cg.shared.global [%0], [%1], 16;" :: "r"(dst), "l"(src));
}

// split-store one feature value into hi/lo bf16 buffers
#define SPLIT_STORE(i, v) do {                                         \
    float _v = (v);                                                    \
    __nv_bfloat16 _h = __float2bfloat16(_v);                           \
    float _hf = __bfloat162float(_h);                                  \
    __nv_bfloat16 _l = __float2bfloat16(_v - _hf);                     \
    *(__nv_bfloat16*)(smc + fh_n + (i) * 272 + pos2) = _h;             \
    *(__nv_bfloat16*)(smc + fl_n + (i) * 272 + pos2) = _l;             \
} while (0)

// ---------------- weight prep: split + pad ----------------
__global__ void prep_w(const float* __restrict__ w) {
    int idx = blockIdx.x * 256 + threadIdx.x;
    if (idx >= NC * NOC * WSTRIDE) return;
    int k = idx % WSTRIDE;
    int o = (idx / WSTRIDE) % NOC;
    int c = idx / (WSTRIDE * NOC);
    float v = (k < 54) ? w[(o * NC + c) * 54 + k] : 0.0f;
    __nv_bfloat16 h = __float2bfloat16(v);
    __nv_bfloat16 l = __float2bfloat16(v - __bfloat162float(h));
    g_Wh[idx] = h;
    g_Wl[idx] = l;
}

// ---------------- main fused kernel ----------------
__global__ void __launch_bounds__(256, 1)
soc_hmma_kernel(const float* __restrict__ x, float* __restrict__ out) {
    extern __shared__ char smc[];
    const uint32_t smb = smem_u32(smc);
    const int tid  = threadIdx.x;
    const int wid  = tid >> 5;
    const int lane = tid & 31;

    const int bx = blockIdx.x;
    const int bb = bx / TILES_PER_IMG;
    const int t  = bx - bb * TILES_PER_IMG;
    const int th = t / NTW;
    const int h0 = th * TILE_H;
    const int w0 = (t - th * NTW) * TILE_W;
    const float* xb = x + (size_t)bb * NC * XCH;

    // warp tile: 64 oc x 32 pos
    const int m0 = (wid & 1) * 64;
    const int n0 = (wid >> 1) * 32;

    // featgen identity: 2 threads per position
    const int pos  = tid & 127;
    const int half = tid >> 7;
    const int pr = pos >> 4, pc = pos & 15;
    const int pos2 = pos * 2;

    // tap offsets (within a channel plane), -1 if out of image
    int offv[9];
#pragma unroll
    for (int kh = 0; kh < 3; ++kh)
#pragma unroll
        for (int kw = 0; kw < 3; ++kw) {
            int gh = h0 + pr - 1 + kh;
            int gw = w0 + pc - 1 + kw;
            offv[kh * 3 + kw] =
                ((unsigned)gh < IH && (unsigned)gw < IW) ? gh * IW + gw : -1;
        }

    // zero F pad rows 54..63 of all four F buffers (never written again)
    for (int i = tid; i < 680; i += 256) {
        int o = 54 * 272 + i * 4;
        *(uint32_t*)(smc + SM_FH0 + o) = 0;
        *(uint32_t*)(smc + SM_FL0 + o) = 0;
        *(uint32_t*)(smc + SM_FH1 + o) = 0;
        *(uint32_t*)(smc + SM_FL1 + o) = 0;
    }

    // ---- prologue: stage channel 0 ----
    {
        const char* sh = (const char*)g_Wh;
        const char* sl = (const char*)g_Wl;
#pragma unroll
        for (int i = 0; i < 5; ++i) {
            int e = tid + i * 256;
            if (e < W_CHUNKS) {
                cpasync16(smb + SM_WH0 + e * 16, sh + e * 16);
                cpasync16(smb + SM_WL0 + e * 16, sl + e * 16);
            }
        }
        asm volatile("cp.async.commit_group;");
    }
    float t9p[9];
    {
        const float* xc = xb;  // channel 0
#pragma unroll
        for (int j = 0; j < 9; ++j) t9p[j] = (offv[j] >= 0) ? xc[offv[j]] : 0.0f;
    }
    // featgen channel 0 into F0
    {
        const uint32_t fh_n = SM_FH0, fl_n = SM_FL0;
        const float* t9 = t9p;
        if (half == 0) {
#pragma unroll
            for (int i = 0; i < 9; ++i) { SPLIT_STORE(i, t9[i]); SPLIT_STORE(9 + i, t9[i] * t9[i]); }
#pragma unroll
            for (int i = 0; i < 8; ++i) SPLIT_STORE(18 + i, t9[i] * t9[i + 1]);
            SPLIT_STORE(26, t9[0] * t9[2]);
        } else {
#pragma unroll
            for (int i = 1; i < 7; ++i) SPLIT_STORE(26 + i, t9[i] * t9[i + 2]);
#pragma unroll
            for (int i = 0; i < 6; ++i) SPLIT_STORE(33 + i, t9[i] * t9[i + 3]);
#pragma unroll
            for (int i = 0; i < 5; ++i) SPLIT_STORE(39 + i, t9[i] * t9[i + 4]);
#pragma unroll
            for (int i = 0; i < 4; ++i) SPLIT_STORE(44 + i, t9[i] * t9[i + 5]);
#pragma unroll
            for (int i = 0; i < 3; ++i) SPLIT_STORE(48 + i, t9[i] * t9[i + 6]);
            SPLIT_STORE(51, t9[0] * t9[7]);
            SPLIT_STORE(52, t9[1] * t9[8]);
            SPLIT_STORE(53, t9[0] * t9[8]);
        }
    }
    // prefetch taps for channel 1
    {
        const float* xc = xb + XCH;
#pragma unroll
        for (int j = 0; j < 9; ++j) t9p[j] = (offv[j] >= 0) ? xc[offv[j]] : 0.0f;
    }
    asm volatile("cp.async.wait_group 0;" ::: "memory");
    __syncthreads();

    // ldmatrix lane-invariant offsets
    const uint32_t aoff = (uint32_t)((m0 + (lane & 15)) * 144 + (lane >> 4) * 16);
    const uint32_t boff = (uint32_t)((lane & 15) * 272 + n0 * 2);

    float acc[4][4][4];
#pragma unroll
    for (int i = 0; i < 4; ++i)
#pragma unroll
        for (int j = 0; j < 4; ++j)
#pragma unroll
            for (int k = 0; k < 4; ++k) acc[i][j][k] = 0.0f;

    // ---- main loop over channels ----
    for (int c = 0; c < NC; ++c) {
        const int buf = c & 1;
        const uint32_t wh = buf ? SM_WH1 : SM_WH0;
        const uint32_t wl = buf ? SM_WL1 : SM_WL0;
        const uint32_t fh = buf ? SM_FH1 : SM_FH0;
        const uint32_t fl = buf ? SM_FL1 : SM_FL0;

        if (c < NC - 1) {
            // cp.async weights for c+1 into the other buffer
            const char* sh = (const char*)(g_Wh + (size_t)(c + 1) * NOC * WSTRIDE);
            const char* sl = (const char*)(g_Wl + (size_t)(c + 1) * NOC * WSTRIDE);
            const uint32_t dwh = smb + (buf ? SM_WH0 : SM_WH1);
            const uint32_t dwl = smb + (buf ? SM_WL0 : SM_WL1);
#pragma unroll
            for (int i = 0; i < 5; ++i) {
                int e = tid + i * 256;
                if (e < W_CHUNKS) {
                    cpasync16(dwh + e * 16, sh + e * 16);
                    cpasync16(dwl + e * 16, sl + e * 16);
                }
            }
            asm volatile("cp.async.commit_group;");

            // featgen channel c+1 into the other F buffer
            const uint32_t fh_n = buf ? SM_FH0 : SM_FH1;
            const uint32_t fl_n = buf ? SM_FL0 : SM_FL1;
            const float* t9 = t9p;
            if (half == 0) {
#pragma unroll
                for (int i = 0; i < 9; ++i) { SPLIT_STORE(i, t9[i]); SPLIT_STORE(9 + i, t9[i] * t9[i]); }
#pragma unroll
                for (int i = 0; i < 8; ++i) SPLIT_STORE(18 + i, t9[i] * t9[i + 1]);
                SPLIT_STORE(26, t9[0] * t9[2]);
            } else {
#pragma unroll
                for (int i = 1; i < 7; ++i) SPLIT_STORE(26 + i, t9[i] * t9[i + 2]);
#pragma unroll
                for (int i = 0; i < 6; ++i) SPLIT_STORE(33 + i, t9[i] * t9[i + 3]);
#pragma unroll
                for (int i = 0; i < 5; ++i) SPLIT_STORE(39 + i, t9[i] * t9[i + 4]);
#pragma unroll
                for (int i = 0; i < 4; ++i) SPLIT_STORE(44 + i, t9[i] * t9[i + 5]);
#pragma unroll
                for (int i = 0; i < 3; ++i) SPLIT_STORE(48 + i, t9[i] * t9[i + 6]);
                SPLIT_STORE(51, t9[0] * t9[7]);
                SPLIT_STORE(52, t9[1] * t9[8]);
                SPLIT_STORE(53, t9[0] * t9[8]);
            }
        }
        if (c < NC - 2) {
            const float* xc = xb + (size_t)(c + 2) * XCH;
#pragma unroll
            for (int j = 0; j < 9; ++j) t9p[j] = (offv[j] >= 0) ? xc[offv[j]] : 0.0f;
        }

        // ---- MMA over current buffers: 4 ksteps x 16 tiles x 3 terms ----
#pragma unroll
        for (int ks = 0; ks < 4; ++ks) {
            uint32_t ah[4][4], al[4][4], bh[4][2], bl[4][2];
#pragma unroll
            for (int mt = 0; mt < 4; ++mt) {
                uint32_t a = smb + aoff + (uint32_t)(mt * 2304 + ks * 32);
                ldsm_x4(ah[mt], a + wh);
                ldsm_x4(al[mt], a + wl);
            }
#pragma unroll
            for (int nt = 0; nt < 4; ++nt) {
                uint32_t b = smb + boff + (uint32_t)(ks * 4352 + nt * 16);
                ldsm_x2t(bh[nt], b + fh);
                ldsm_x2t(bl[nt], b + fl);
            }
#pragma unroll
            for (int mt = 0; mt < 4; ++mt)
#pragma unroll
                for (int nt = 0; nt < 4; ++nt) {
                    mma16816(acc[mt][nt], ah[mt], bh[nt]);
                    mma16816(acc[mt][nt], al[mt], bh[nt]);
                    mma16816(acc[mt][nt], ah[mt], bl[nt]);
                }
        }

        if (c < NC - 1) asm volatile("cp.async.wait_group 0;" ::: "memory");
        __syncthreads();
    }

    // ---- epilogue: direct register -> global stores (float2, coalesced) ----
    const int l4 = lane >> 2;
    const int l2 = (lane & 3) * 2;
#pragma unroll
    for (int mt = 0; mt < 4; ++mt) {
#pragma unroll
        for (int nt = 0; nt < 4; ++nt) {
            int oc = m0 + 16 * mt + l4;
            int p  = n0 + 8 * nt + l2;
            int hh = h0 + (p >> 4);
            int ww = w0 + (p & 15);
            float* p0 = out + (((size_t)(bb * NOC + oc) * IH + hh) * IW + ww);
            float2 v0 = make_float2(acc[mt][nt][0], acc[mt][nt][1]);
            float2 v1 = make_float2(acc[mt][nt][2], acc[mt][nt][3]);
            *(float2*)p0 = v0;
            *(float2*)(p0 + (size_t)8 * IH * IW) = v1;  // oc + 8
        }
    }
}

extern "C" void kernel_launch(void* const* d_in, const int* in_sizes, int n_in,
                              void* d_out, int out_size) {
    const float* x = (const float*)d_in[0];  // [8, 64, 96, 96]
    const float* w = (const float*)d_in[1];  // [128, 64, 54, 1]
    float* out = (float*)d_out;              // [8, 128, 96, 96]
    (void)in_sizes; (void)n_in; (void)out_size;

    cudaFuncSetAttribute(soc_hmma_kernel,
                         cudaFuncAttributeMaxDynamicSharedMemorySize, SM_TOTAL);

    prep_w<<<(NC * NOC * WSTRIDE + 255) / 256, 256>>>(w);
    soc_hmma_kernel<<<NB * TILES_PER_IMG, 256, SM_TOTAL>>>(x, out);
}

// round 6
// speedup vs baseline: 6.1063x; 3.1667x over previous
#include <cuda_runtime.h>
#include <cuda_fp16.h>
#include <cstdint>

// Second-order conv2d as fused fp16 implicit GEMM on mma.sync (HMMA).
// out[oc,pos] = sum_k W[oc,k] * F[k,pos]; K = 32 channel-pairs x 108 (pad 112).
// Single-term fp16 (11 mantissa bits): output rel err ~2.5e-4 < 1e-3.

#define NB 8
#define NC 64
#define NOC 128
#define IH 96
#define IW 96
#define XCH (IH * IW)
#define NTW 6
#define TILES_PER_IMG 72
#define NPAIR 32
#define KP 112                  // padded K per pair (7 ksteps of 16)
#define WROW 120                // fp16 elems per oc row in g_W / smem W (240 B, conflict-free)
#define FROWB 272               // bytes per F k-row (256 B data + 16 pad, conflict-free)

// ---- SMEM layout (bytes) ----
#define SM_W   0                             // 128 * 240        = 30720
#define SM_F0  30720                         // 112 * 272        = 30464
#define SM_F1  (30720 + 30464)               // 61184
#define SM_TOTAL (SM_F1 + 30464)             // 91648

#define W_TILE_B 30720
#define W_CHUNKS (W_TILE_B / 16)             // 1920

// Pre-padded fp16 weights: [pair][128 oc][120], cols 108..119 zero.
__device__ __align__(16) __half g_W[NPAIR * NOC * WROW];

// ---------------- helpers ----------------
__device__ __forceinline__ uint32_t smem_u32(const void* p) {
    uint32_t a;
    asm("{ .reg .u64 t; cvta.to.shared.u64 t, %1; cvt.u32.u64 %0, t; }" : "=r"(a) : "l"(p));
    return a;
}

__device__ __forceinline__ void ldsm_x4(uint32_t* r, uint32_t addr) {
    asm volatile("ldmatrix.sync.aligned.m8n8.x4.shared.b16 {%0,%1,%2,%3}, [%4];"
                 : "=r"(r[0]), "=r"(r[1]), "=r"(r[2]), "=r"(r[3]) : "r"(addr));
}

__device__ __forceinline__ void ldsm_x2t(uint32_t* r, uint32_t addr) {
    asm volatile("ldmatrix.sync.aligned.m8n8.x2.trans.shared.b16 {%0,%1}, [%2];"
                 : "=r"(r[0]), "=r"(r[1]) : "r"(addr));
}

__device__ __forceinline__ void mma16816(float* d, const uint32_t* a, const uint32_t* b) {
    asm volatile(
        "mma.sync.aligned.m16n8k16.row.col.f32.f16.f16.f32 "
        "{%0,%1,%2,%3}, {%4,%5,%6,%7}, {%8,%9}, {%0,%1,%2,%3};"
        : "+f"(d[0]), "+f"(d[1]), "+f"(d[2]), "+f"(d[3])
        : "r"(a[0]), "r"(a[1]), "r"(a[2]), "r"(a[3]), "r"(b[0]), "r"(b[1]));
}

__device__ __forceinline__ void cpasync16(uint32_t dst, const void* src) {
    asm volatile("cp.async.cg.shared.global [%0], [%1], 16;" :: "r"(dst), "l"(src));
}

// store one fp16 feature into F buffer at row (cc*54 + i), col pos
#define FSTORE(i, v) \
    *(__half*)(smc + fbase + (uint32_t)((cc54 + (i)) * FROWB) + pos2) = __float2half(v)

#define FEATGEN(fb) do {                                                     \
    const uint32_t fbase = (fb);                                             \
    const float* t9 = t9p;                                                   \
    _Pragma("unroll")                                                        \
    for (int i = 0; i < 9; ++i) { FSTORE(i, t9[i]); FSTORE(9 + i, t9[i] * t9[i]); } \
    _Pragma("unroll")                                                        \
    for (int i = 0; i < 8; ++i) FSTORE(18 + i, t9[i] * t9[i + 1]);           \
    _Pragma("unroll")                                                        \
    for (int i = 0; i < 7; ++i) FSTORE(26 + i, t9[i] * t9[i + 2]);           \
    _Pragma("unroll")                                                        \
    for (int i = 0; i < 6; ++i) FSTORE(33 + i, t9[i] * t9[i + 3]);           \
    _Pragma("unroll")                                                        \
    for (int i = 0; i < 5; ++i) FSTORE(39 + i, t9[i] * t9[i + 4]);           \
    _Pragma("unroll")                                                        \
    for (int i = 0; i < 4; ++i) FSTORE(44 + i, t9[i] * t9[i + 5]);           \
    _Pragma("unroll")                                                        \
    for (int i = 0; i < 3; ++i) FSTORE(48 + i, t9[i] * t9[i + 6]);           \
    FSTORE(51, t9[0] * t9[7]); FSTORE(52, t9[1] * t9[8]);                    \
    FSTORE(53, t9[0] * t9[8]);                                               \
} while (0)

// ---------------- weight prep: pad + convert ----------------
__global__ void prep_w(const float* __restrict__ w) {
    int idx = blockIdx.x * 256 + threadIdx.x;
    if (idx >= NPAIR * NOC * WROW) return;
    int k = idx % WROW;
    int o = (idx / WROW) % NOC;
    int p = idx / (WROW * NOC);
    float v = 0.0f;
    if (k < 108) {
        int c = 2 * p + k / 54, f = k % 54;
        v = w[(o * NC + c) * 54 + f];
    }
    g_W[idx] = __float2half(v);
}

// ---------------- main fused kernel ----------------
__global__ void __launch_bounds__(256, 2)
soc_fp16_kernel(const float* __restrict__ x, float* __restrict__ out) {
    extern __shared__ char smc[];
    const uint32_t smb = smem_u32(smc);
    const int tid  = threadIdx.x;
    const int wid  = tid >> 5;
    const int lane = tid & 31;

    const int bx = blockIdx.x;
    const int bb = bx / TILES_PER_IMG;
    const int t  = bx - bb * TILES_PER_IMG;
    const int th = t / NTW;
    const int h0 = th * 8;
    const int w0 = (t - th * NTW) * 16;
    const float* xb = x + (size_t)bb * NC * XCH;

    // warp tile: 64 oc x 32 pos
    const int m0 = (wid & 1) * 64;
    const int n0 = (wid >> 1) * 32;

    // featgen identity: thread -> (pos, channel-of-pair)
    const int pos = tid & 127;
    const int cc  = tid >> 7;            // 0/1: channel within pair
    const int pr  = pos >> 4, pc = pos & 15;
    const uint32_t pos2 = (uint32_t)(pos * 2);
    const uint32_t cc54 = (uint32_t)(cc * 54);

    // tap offsets within one channel plane (-1 = zero pad)
    int offv[9];
#pragma unroll
    for (int kh = 0; kh < 3; ++kh)
#pragma unroll
        for (int kw = 0; kw < 3; ++kw) {
            int gh = h0 + pr - 1 + kh;
            int gw = w0 + pc - 1 + kw;
            offv[kh * 3 + kw] =
                ((unsigned)gh < IH && (unsigned)gw < IW) ? gh * IW + gw : -1;
        }

    // zero F pad rows 108..111 of both buffers (written once)
    for (int i = tid; i < 272; i += 256) {
        ((uint32_t*)(smc + SM_F0 + 108 * FROWB))[i] = 0;
        ((uint32_t*)(smc + SM_F1 + 108 * FROWB))[i] = 0;
    }

    // ---- prologue: W0 copy + featgen pair 0 ----
    {
        const char* src = (const char*)g_W;
#pragma unroll
        for (int i = 0; i < 8; ++i) {
            int e = tid + i * 256;
            if (e < W_CHUNKS) cpasync16(smb + SM_W + e * 16, src + e * 16);
        }
        asm volatile("cp.async.commit_group;");
    }
    float t9p[9];
    {
        const float* xc = xb + (size_t)cc * XCH;  // pair 0
#pragma unroll
        for (int j = 0; j < 9; ++j) t9p[j] = (offv[j] >= 0) ? xc[offv[j]] : 0.0f;
    }
    FEATGEN(SM_F0);
    {
        const float* xc = xb + (size_t)(2 + cc) * XCH;  // pair 1
#pragma unroll
        for (int j = 0; j < 9; ++j) t9p[j] = (offv[j] >= 0) ? xc[offv[j]] : 0.0f;
    }
    asm volatile("cp.async.wait_group 0;" ::: "memory");
    __syncthreads();

    // lane-invariant ldmatrix offsets
    const uint32_t aoff = smb + SM_W + (uint32_t)((m0 + (lane & 15)) * 240 + (lane >> 4) * 16);
    const uint32_t boff = (uint32_t)((lane & 15) * FROWB + n0 * 2);

    float acc[4][4][4];
#pragma unroll
    for (int i = 0; i < 4; ++i)
#pragma unroll
        for (int j = 0; j < 4; ++j)
#pragma unroll
            for (int k = 0; k < 4; ++k) acc[i][j][k] = 0.0f;

    // ---- main loop over channel pairs ----
    for (int p = 0; p < NPAIR; ++p) {
        const uint32_t fcur = smb + ((p & 1) ? SM_F1 : SM_F0);

        // MMA: 7 ksteps x (4 mtiles x 4 ntiles)
#pragma unroll
        for (int ks = 0; ks < 7; ++ks) {
            uint32_t ah[4][4], bh[4][2];
#pragma unroll
            for (int mt = 0; mt < 4; ++mt)
                ldsm_x4(ah[mt], aoff + (uint32_t)(mt * 16 * 240 + ks * 32));
#pragma unroll
            for (int nt = 0; nt < 4; ++nt)
                ldsm_x2t(bh[nt], fcur + boff + (uint32_t)(ks * 16 * FROWB + nt * 16));
#pragma unroll
            for (int mt = 0; mt < 4; ++mt)
#pragma unroll
                for (int nt = 0; nt < 4; ++nt)
                    mma16816(acc[mt][nt], ah[mt], bh[nt]);
        }

        if (p < NPAIR - 1) {
            __syncthreads();  // all warps done with W(p) reads and F(p+1 buffer) reads

            // stage W(p+1) (overlaps featgen below)
            const char* src = (const char*)g_W + (size_t)(p + 1) * W_TILE_B;
#pragma unroll
            for (int i = 0; i < 8; ++i) {
                int e = tid + i * 256;
                if (e < W_CHUNKS) cpasync16(smb + SM_W + e * 16, src + e * 16);
            }
            asm volatile("cp.async.commit_group;");

            // featgen pair p+1 into the other F buffer
            FEATGEN((p & 1) ? SM_F0 : SM_F1);

            // prefetch taps for pair p+2
            if (p < NPAIR - 2) {
                const float* xc = xb + (size_t)(2 * (p + 2) + cc) * XCH;
#pragma unroll
                for (int j = 0; j < 9; ++j)
                    t9p[j] = (offv[j] >= 0) ? xc[offv[j]] : 0.0f;
            }

            asm volatile("cp.async.wait_group 0;" ::: "memory");
            __syncthreads();
        }
    }

    // ---- epilogue: direct register -> global float2 stores ----
    const int l4 = lane >> 2;
    const int l2 = (lane & 3) * 2;
#pragma unroll
    for (int mt = 0; mt < 4; ++mt) {
#pragma unroll
        for (int nt = 0; nt < 4; ++nt) {
            int oc = m0 + 16 * mt + l4;
            int p  = n0 + 8 * nt + l2;
            int hh = h0 + (p >> 4);
            int ww = w0 + (p & 15);
            float* p0 = out + (((size_t)(bb * NOC + oc) * IH + hh) * IW + ww);
            *(float2*)p0 = make_float2(acc[mt][nt][0], acc[mt][nt][1]);
            *(float2*)(p0 + (size_t)8 * IH * IW) =
                make_float2(acc[mt][nt][2], acc[mt][nt][3]);  // oc + 8
        }
    }
}

extern "C" void kernel_launch(void* const* d_in, const int* in_sizes, int n_in,
                              void* d_out, int out_size) {
    const float* x = (const float*)d_in[0];  // [8, 64, 96, 96]
    const float* w = (const float*)d_in[1];  // [128, 64, 54, 1]
    float* out = (float*)d_out;              // [8, 128, 96, 96]
    (void)in_sizes; (void)n_in; (void)out_size;

    cudaFuncSetAttribute(soc_fp16_kernel,
                         cudaFuncAttributeMaxDynamicSharedMemorySize, SM_TOTAL);

    prep_w<<<(NPAIR * NOC * WROW + 255) / 256, 256>>>(w);
    soc_fp16_kernel<<<NB * TILES_PER_IMG, 256, SM_TOTAL>>>(x, out);
}

// round 7
// speedup vs baseline: 6.6225x; 1.0845x over previous
#include <cuda_runtime.h>
#include <cuda_fp16.h>
#include <cstdint>

// Second-order conv2d as fused fp16 implicit GEMM on mma.sync (HMMA).
// CTA tile 128 oc x 256 pos, warp tile 64x64, occ 1, fully double-buffered,
// one __syncthreads per channel-pair.

#define NB 8
#define NC 64
#define NOC 128
#define IH 96
#define IW 96
#define XCH (IH * IW)
#define NTW 3                   // 96 / 32
#define TILES_PER_IMG 36        // 12 x 3
#define NPAIR 32
#define WROW 120                // fp16 per oc row (240 B; 8-row bank-shift OK)
#define WROWB 240
#define FROWB 528               // bytes per F k-row (256 pos * 2B + 16 pad)

// ---- SMEM layout (bytes) ----
#define SM_W0 0                          // 128*240 = 30720
#define SM_W1 30720
#define SM_F0 61440                      // 112*528 = 59136
#define SM_F1 120576
#define SM_TOTAL 179712

#define W_TILE_B 30720
#define W_CHUNKS (W_TILE_B / 16)         // 1920

// Pre-padded fp16 weights: [pair][128 oc][120], cols 108..119 zero.
__device__ __align__(16) __half g_W[NPAIR * NOC * WROW];

// ---------------- helpers ----------------
__device__ __forceinline__ uint32_t smem_u32(const void* p) {
    uint32_t a;
    asm("{ .reg .u64 t; cvta.to.shared.u64 t, %1; cvt.u32.u64 %0, t; }" : "=r"(a) : "l"(p));
    return a;
}

__device__ __forceinline__ void ldsm_x4(uint32_t* r, uint32_t addr) {
    asm volatile("ldmatrix.sync.aligned.m8n8.x4.shared.b16 {%0,%1,%2,%3}, [%4];"
                 : "=r"(r[0]), "=r"(r[1]), "=r"(r[2]), "=r"(r[3]) : "r"(addr));
}

__device__ __forceinline__ void ldsm_x2t(uint32_t* r, uint32_t addr) {
    asm volatile("ldmatrix.sync.aligned.m8n8.x2.trans.shared.b16 {%0,%1}, [%2];"
                 : "=r"(r[0]), "=r"(r[1]) : "r"(addr));
}

__device__ __forceinline__ void mma16816(float* d, const uint32_t* a, const uint32_t* b) {
    asm volatile(
        "mma.sync.aligned.m16n8k16.row.col.f32.f16.f16.f32 "
        "{%0,%1,%2,%3}, {%4,%5,%6,%7}, {%8,%9}, {%0,%1,%2,%3};"
        : "+f"(d[0]), "+f"(d[1]), "+f"(d[2]), "+f"(d[3])
        : "r"(a[0]), "r"(a[1]), "r"(a[2]), "r"(a[3]), "r"(b[0]), "r"(b[1]));
}

__device__ __forceinline__ void cpasync16(uint32_t dst, const void* src) {
    asm volatile("cp.async.cg.shared.global [%0], [%1], 16;" :: "r"(dst), "l"(src));
}

// ---------------- weight prep: pad + convert ----------------
__global__ void prep_w(const float* __restrict__ w) {
    int idx = blockIdx.x * 256 + threadIdx.x;
    if (idx >= NPAIR * NOC * WROW) return;
    int k = idx % WROW;
    int o = (idx / WROW) % NOC;
    int p = idx / (WROW * NOC);
    float v = 0.0f;
    if (k < 108) {
        int c = 2 * p + k / 54, f = k % 54;
        v = w[(o * NC + c) * 54 + f];
    }
    g_W[idx] = __float2half(v);
}

// featgen: 54 features of one channel -> F rows [row0..row0+53] at column pos
__device__ __forceinline__ void featgen_ch(char* smc, uint32_t base, const float* t9) {
#define FST(i, v) *(__half*)(smc + base + (uint32_t)((i) * FROWB)) = __float2half(v)
#pragma unroll
    for (int i = 0; i < 9; ++i) { FST(i, t9[i]); FST(9 + i, t9[i] * t9[i]); }
#pragma unroll
    for (int i = 0; i < 8; ++i) FST(18 + i, t9[i] * t9[i + 1]);
#pragma unroll
    for (int i = 0; i < 7; ++i) FST(26 + i, t9[i] * t9[i + 2]);
#pragma unroll
    for (int i = 0; i < 6; ++i) FST(33 + i, t9[i] * t9[i + 3]);
#pragma unroll
    for (int i = 0; i < 5; ++i) FST(39 + i, t9[i] * t9[i + 4]);
#pragma unroll
    for (int i = 0; i < 4; ++i) FST(44 + i, t9[i] * t9[i + 5]);
#pragma unroll
    for (int i = 0; i < 3; ++i) FST(48 + i, t9[i] * t9[i + 6]);
    FST(51, t9[0] * t9[7]); FST(52, t9[1] * t9[8]); FST(53, t9[0] * t9[8]);
#undef FST
}

// ---------------- main fused kernel ----------------
__global__ void __launch_bounds__(256, 1)
soc_fp16_kernel(const float* __restrict__ x, float* __restrict__ out) {
    extern __shared__ char smc[];
    const uint32_t smb = smem_u32(smc);
    const int tid  = threadIdx.x;
    const int wid  = tid >> 5;
    const int lane = tid & 31;

    const int bx = blockIdx.x;
    const int bb = bx / TILES_PER_IMG;
    const int t  = bx - bb * TILES_PER_IMG;
    const int th = t / NTW;
    const int h0 = th * 8;
    const int w0 = (t - th * NTW) * 32;
    const float* xb = x + (size_t)bb * NC * XCH;

    // warp tile: 64 oc x 64 pos
    const int m0 = (wid & 1) * 64;
    const int n0 = (wid >> 1) * 64;

    // featgen identity: 1 thread per position, both channels of the pair
    const int pos = tid;                 // 0..255
    const int prr = pos >> 5, pcc = pos & 31;
    const uint32_t pos2 = (uint32_t)(pos * 2);

    // tap offsets within one channel plane (-1 = zero pad)
    int offv[9];
#pragma unroll
    for (int kh = 0; kh < 3; ++kh)
#pragma unroll
        for (int kw = 0; kw < 3; ++kw) {
            int gh = h0 + prr - 1 + kh;
            int gw = w0 + pcc - 1 + kw;
            offv[kh * 3 + kw] =
                ((unsigned)gh < IH && (unsigned)gw < IW) ? gh * IW + gw : -1;
        }

    // zero F pad rows 108..111 of both buffers
    for (int i = tid; i < 528; i += 256) {
        ((uint32_t*)(smc + SM_F0 + 108 * FROWB))[i] = 0;
        ((uint32_t*)(smc + SM_F1 + 108 * FROWB))[i] = 0;
    }

    // ---- prologue ----
    {   // cp.async W(0) -> buf0
        const char* src = (const char*)g_W;
#pragma unroll
        for (int i = 0; i < 8; ++i) {
            int e = tid + i * 256;
            if (e < W_CHUNKS) cpasync16(smb + SM_W0 + e * 16, src + e * 16);
        }
        asm volatile("cp.async.commit_group;");
    }
    float t9a[9], t9b[9];
#pragma unroll
    for (int j = 0; j < 9; ++j) {        // taps pair 0
        t9a[j] = (offv[j] >= 0) ? xb[offv[j]] : 0.0f;
        t9b[j] = (offv[j] >= 0) ? xb[XCH + offv[j]] : 0.0f;
    }
    featgen_ch(smc, SM_F0 + pos2, t9a);
    featgen_ch(smc, SM_F0 + 54 * FROWB + pos2, t9b);
#pragma unroll
    for (int j = 0; j < 9; ++j) {        // taps pair 1
        t9a[j] = (offv[j] >= 0) ? xb[2 * XCH + offv[j]] : 0.0f;
        t9b[j] = (offv[j] >= 0) ? xb[3 * XCH + offv[j]] : 0.0f;
    }
    asm volatile("cp.async.wait_group 0;" ::: "memory");
    __syncthreads();

    // lane-invariant ldmatrix offsets (relative to buffer base)
    const uint32_t aoff = (uint32_t)((m0 + (lane & 15)) * WROWB + (lane >> 4) * 16);
    const uint32_t boff = (uint32_t)((lane & 15) * FROWB + n0 * 2);

    float acc[4][8][4];
#pragma unroll
    for (int i = 0; i < 4; ++i)
#pragma unroll
        for (int j = 0; j < 8; ++j)
#pragma unroll
            for (int k = 0; k < 4; ++k) acc[i][j][k] = 0.0f;

    // ---- main loop over channel pairs (one __syncthreads per pair) ----
    for (int p = 0; p < NPAIR; ++p) {
        const uint32_t wcur = smb + ((p & 1) ? SM_W1 : SM_W0);
        const uint32_t fcur = smb + ((p & 1) ? SM_F1 : SM_F0);

        // stage W(p+1) into the other W buffer (freed by last pair's sync)
        if (p < NPAIR - 1) {
            const char* src = (const char*)g_W + (size_t)(p + 1) * W_TILE_B;
            const uint32_t dst = smb + ((p & 1) ? SM_W0 : SM_W1);
#pragma unroll
            for (int i = 0; i < 8; ++i) {
                int e = tid + i * 256;
                if (e < W_CHUNKS) cpasync16(dst + e * 16, src + e * 16);
            }
            asm volatile("cp.async.commit_group;");
        }

        // MMA: 7 ksteps x (4 mtiles x 8 ntiles)
#pragma unroll
        for (int ks = 0; ks < 7; ++ks) {
            uint32_t ah[4][4], bh[8][2];
#pragma unroll
            for (int mt = 0; mt < 4; ++mt)
                ldsm_x4(ah[mt], wcur + aoff + (uint32_t)(mt * 16 * WROWB + ks * 32));
#pragma unroll
            for (int nt = 0; nt < 8; ++nt)
                ldsm_x2t(bh[nt], fcur + boff + (uint32_t)(ks * 16 * FROWB + nt * 16));
#pragma unroll
            for (int mt = 0; mt < 4; ++mt)
#pragma unroll
                for (int nt = 0; nt < 8; ++nt)
                    mma16816(acc[mt][nt], ah[mt], bh[nt]);
        }

        if (p < NPAIR - 1) {
            // featgen pair p+1 into the other F buffer (WAR safe: sync at end of p-1)
            const uint32_t fnxt = (p & 1) ? SM_F0 : SM_F1;
            featgen_ch(smc, fnxt + pos2, t9a);
            featgen_ch(smc, fnxt + 54 * FROWB + pos2, t9b);

            // reload taps for pair p+2 (latency hidden under next MMA)
            if (p + 2 < NPAIR) {
                const float* xc = xb + (size_t)(2 * (p + 2)) * XCH;
#pragma unroll
                for (int j = 0; j < 9; ++j) {
                    t9a[j] = (offv[j] >= 0) ? xc[offv[j]] : 0.0f;
                    t9b[j] = (offv[j] >= 0) ? xc[XCH + offv[j]] : 0.0f;
                }
            }

            asm volatile("cp.async.wait_group 0;" ::: "memory");
            __syncthreads();
        }
    }

    // ---- epilogue: direct register -> global float2 stores ----
    const int l4 = lane >> 2;
    const int l2 = (lane & 3) * 2;
#pragma unroll
    for (int mt = 0; mt < 4; ++mt) {
#pragma unroll
        for (int nt = 0; nt < 8; ++nt) {
            int oc = m0 + 16 * mt + l4;
            int pp = n0 + 8 * nt + l2;
            int hh = h0 + (pp >> 5);
            int ww = w0 + (pp & 31);
            float* p0 = out + (((size_t)(bb * NOC + oc) * IH + hh) * IW + ww);
            *(float2*)p0 = make_float2(acc[mt][nt][0], acc[mt][nt][1]);
            *(float2*)(p0 + (size_t)8 * IH * IW) =
                make_float2(acc[mt][nt][2], acc[mt][nt][3]);  // oc + 8
        }
    }
}

extern "C" void kernel_launch(void* const* d_in, const int* in_sizes, int n_in,
                              void* d_out, int out_size) {
    const float* x = (const float*)d_in[0];  // [8, 64, 96, 96]
    const float* w = (const float*)d_in[1];  // [128, 64, 54, 1]
    float* out = (float*)d_out;              // [8, 128, 96, 96]
    (void)in_sizes; (void)n_in; (void)out_size;

    cudaFuncSetAttribute(soc_fp16_kernel,
                         cudaFuncAttributeMaxDynamicSharedMemorySize, SM_TOTAL);

    prep_w<<<(NPAIR * NOC * WROW + 255) / 256, 256>>>(w);
    soc_fp16_kernel<<<NB * TILES_PER_IMG, 256, SM_TOTAL>>>(x, out);
}

// round 8
// speedup vs baseline: 7.2237x; 1.0908x over previous
#include <cuda_runtime.h>
#include <cuda_fp16.h>
#include <cstdint>

// Second-order conv2d as fused fp16 implicit GEMM on mma.sync (HMMA).
// CTA tile 128 oc x 256 pos, warp tile 64x64, occ 1, fully double-buffered,
// one __syncthreads per channel-pair. F stored [pos][k] (vectorized featgen,
// non-trans ldmatrix for B).

#define NB 8
#define NC 64
#define NOC 128
#define IH 96
#define IW 96
#define XCH (IH * IW)
#define NTW 3                   // 96 / 32
#define TILES_PER_IMG 36        // 12 x 3
#define NPAIR 32
#define WROWB 240               // bytes per W oc-row (120 fp16)
#define FROWB 240               // bytes per F pos-row (120 fp16: 112 k + 8 pad)

// ---- SMEM layout (bytes) ----
#define SM_W0 0                          // 128*240 = 30720
#define SM_W1 30720
#define SM_F0 61440                      // 256*240 = 61440
#define SM_F1 122880
#define SM_TOTAL 184320

#define W_TILE_B 30720
#define W_CHUNKS (W_TILE_B / 16)         // 1920
#define WROW 120

// Pre-padded fp16 weights: [pair][128 oc][120], cols 108..119 zero.
__device__ __align__(16) __half g_W[NPAIR * NOC * WROW];

// ---------------- helpers ----------------
__device__ __forceinline__ uint32_t smem_u32(const void* p) {
    uint32_t a;
    asm("{ .reg .u64 t; cvta.to.shared.u64 t, %1; cvt.u32.u64 %0, t; }" : "=r"(a) : "l"(p));
    return a;
}

__device__ __forceinline__ void ldsm_x4(uint32_t* r, uint32_t addr) {
    asm volatile("ldmatrix.sync.aligned.m8n8.x4.shared.b16 {%0,%1,%2,%3}, [%4];"
                 : "=r"(r[0]), "=r"(r[1]), "=r"(r[2]), "=r"(r[3]) : "r"(addr));
}

__device__ __forceinline__ void mma16816(float* d, const uint32_t* a, const uint32_t* b) {
    asm volatile(
        "mma.sync.aligned.m16n8k16.row.col.f32.f16.f16.f32 "
        "{%0,%1,%2,%3}, {%4,%5,%6,%7}, {%8,%9}, {%0,%1,%2,%3};"
        : "+f"(d[0]), "+f"(d[1]), "+f"(d[2]), "+f"(d[3])
        : "r"(a[0]), "r"(a[1]), "r"(a[2]), "r"(a[3]), "r"(b[0]), "r"(b[1]));
}

__device__ __forceinline__ void cpasync16(uint32_t dst, const void* src) {
    asm volatile("cp.async.cg.shared.global [%0], [%1], 16;" :: "r"(dst), "l"(src));
}

// feature i (0..53) of one channel's 9 taps; folds to one mul under full unroll
__device__ __forceinline__ float featval(const float* t9, int i) {
    if (i < 9)  return t9[i];
    if (i < 18) return t9[i - 9] * t9[i - 9];
    int r = i - 18, off, base;
    if      (r <  8) { off = 1; base = r; }
    else if (r < 15) { off = 2; base = r - 8; }
    else if (r < 21) { off = 3; base = r - 15; }
    else if (r < 26) { off = 4; base = r - 21; }
    else if (r < 30) { off = 5; base = r - 26; }
    else if (r < 33) { off = 6; base = r - 30; }
    else if (r < 35) { off = 7; base = r - 33; }
    else             { off = 8; base = 0; }
    return t9[base] * t9[base + off];
}

// write one position's 112 k-values (108 features + 4 zeros) as 14 x 16B
__device__ __forceinline__ void featgen_row(char* dst, const float* t9a, const float* t9b) {
#pragma unroll
    for (int v = 0; v < 14; ++v) {
        uint4 q;
        uint32_t* qs = (uint32_t*)&q;
#pragma unroll
        for (int h = 0; h < 4; ++h) {
            int i0 = v * 8 + h * 2, i1 = i0 + 1;
            float f0 = (i0 < 108) ? ((i0 < 54) ? featval(t9a, i0) : featval(t9b, i0 - 54)) : 0.f;
            float f1 = (i1 < 108) ? ((i1 < 54) ? featval(t9a, i1) : featval(t9b, i1 - 54)) : 0.f;
            __half2 hh = __floats2half2_rn(f0, f1);
            qs[h] = *(uint32_t*)&hh;
        }
        *(uint4*)(dst + v * 16) = q;
    }
}

// ---------------- weight prep: pad + convert ----------------
__global__ void prep_w(const float* __restrict__ w) {
    int idx = blockIdx.x * 256 + threadIdx.x;
    if (idx >= NPAIR * NOC * WROW) return;
    int k = idx % WROW;
    int o = (idx / WROW) % NOC;
    int p = idx / (WROW * NOC);
    float v = 0.0f;
    if (k < 108) {
        int c = 2 * p + k / 54, f = k % 54;
        v = w[(o * NC + c) * 54 + f];
    }
    g_W[idx] = __float2half(v);
}

// ---------------- main fused kernel ----------------
__global__ void __launch_bounds__(256, 1)
soc_fp16_kernel(const float* __restrict__ x, float* __restrict__ out) {
    extern __shared__ char smc[];
    const uint32_t smb = smem_u32(smc);
    const int tid  = threadIdx.x;
    const int wid  = tid >> 5;
    const int lane = tid & 31;

    const int bx = blockIdx.x;
    const int bb = bx / TILES_PER_IMG;
    const int t  = bx - bb * TILES_PER_IMG;
    const int th = t / NTW;
    const int h0 = th * 8;
    const int w0 = (t - th * NTW) * 32;
    const float* xb = x + (size_t)bb * NC * XCH;

    // warp tile: 64 oc x 64 pos
    const int m0 = (wid & 1) * 64;
    const int n0 = (wid >> 1) * 64;

    // featgen identity: 1 thread per position (tile 8 rows x 32 cols)
    const int pos = tid;
    const int prr = pos >> 5, pcc = pos & 31;

    int offv[9];
#pragma unroll
    for (int kh = 0; kh < 3; ++kh)
#pragma unroll
        for (int kw = 0; kw < 3; ++kw) {
            int gh = h0 + prr - 1 + kh;
            int gw = w0 + pcc - 1 + kw;
            offv[kh * 3 + kw] =
                ((unsigned)gh < IH && (unsigned)gw < IW) ? gh * IW + gw : -1;
        }

    // ---- prologue ----
    {   // cp.async W(0) -> buf0
        const char* src = (const char*)g_W;
#pragma unroll
        for (int i = 0; i < 8; ++i) {
            int e = tid + i * 256;
            if (e < W_CHUNKS) cpasync16(smb + SM_W0 + e * 16, src + e * 16);
        }
        asm volatile("cp.async.commit_group;");
    }
    float t9a[9], t9b[9];
#pragma unroll
    for (int j = 0; j < 9; ++j) {        // taps pair 0
        t9a[j] = (offv[j] >= 0) ? xb[offv[j]] : 0.0f;
        t9b[j] = (offv[j] >= 0) ? xb[XCH + offv[j]] : 0.0f;
    }
    featgen_row(smc + SM_F0 + pos * FROWB, t9a, t9b);
#pragma unroll
    for (int j = 0; j < 9; ++j) {        // taps pair 1
        t9a[j] = (offv[j] >= 0) ? xb[2 * XCH + offv[j]] : 0.0f;
        t9b[j] = (offv[j] >= 0) ? xb[3 * XCH + offv[j]] : 0.0f;
    }
    asm volatile("cp.async.wait_group 0;" ::: "memory");
    __syncthreads();

    // lane-invariant ldmatrix offsets (relative to buffer base)
    const uint32_t aoff = (uint32_t)((m0 + (lane & 15)) * WROWB + (lane >> 4) * 16);
    // B (non-trans x4): lanes 0-7 m0(rows+0..7,k+0), 8-15 m1(rows,k+16),
    //                   16-23 m2(rows+8,k+0), 24-31 m3(rows+8,k+16)
    const uint32_t boff = (uint32_t)(n0 * FROWB + ((lane >> 4) & 1) * 8 * FROWB +
                                     ((lane >> 3) & 1) * 16 + (lane & 7) * FROWB);

    float acc[4][8][4];
#pragma unroll
    for (int i = 0; i < 4; ++i)
#pragma unroll
        for (int j = 0; j < 8; ++j)
#pragma unroll
            for (int k = 0; k < 4; ++k) acc[i][j][k] = 0.0f;

    // ---- main loop over channel pairs (one __syncthreads per pair) ----
    for (int p = 0; p < NPAIR; ++p) {
        const uint32_t wcur = smb + ((p & 1) ? SM_W1 : SM_W0);
        const uint32_t fcur = smb + ((p & 1) ? SM_F1 : SM_F0);

        // stage W(p+1) into the other W buffer
        if (p < NPAIR - 1) {
            const char* src = (const char*)g_W + (size_t)(p + 1) * W_TILE_B;
            const uint32_t dst = smb + ((p & 1) ? SM_W0 : SM_W1);
#pragma unroll
            for (int i = 0; i < 8; ++i) {
                int e = tid + i * 256;
                if (e < W_CHUNKS) cpasync16(dst + e * 16, src + e * 16);
            }
            asm volatile("cp.async.commit_group;");
        }

        // MMA: 7 ksteps x (4 mtiles x 8 ntiles); B loaded 2 ntiles per ldsm.x4
#pragma unroll
        for (int ks = 0; ks < 7; ++ks) {
            uint32_t ah[4][4], bq[4][4];
#pragma unroll
            for (int mt = 0; mt < 4; ++mt)
                ldsm_x4(ah[mt], wcur + aoff + (uint32_t)(mt * 16 * WROWB + ks * 32));
#pragma unroll
            for (int q = 0; q < 4; ++q)
                ldsm_x4(bq[q], fcur + boff + (uint32_t)(q * 16 * FROWB + ks * 32));
#pragma unroll
            for (int mt = 0; mt < 4; ++mt)
#pragma unroll
                for (int q = 0; q < 4; ++q) {
                    mma16816(acc[mt][2 * q],     ah[mt], &bq[q][0]);
                    mma16816(acc[mt][2 * q + 1], ah[mt], &bq[q][2]);
                }
        }

        if (p < NPAIR - 1) {
            // featgen pair p+1 into the other F buffer
            featgen_row(smc + ((p & 1) ? SM_F0 : SM_F1) + pos * FROWB, t9a, t9b);

            // reload taps for pair p+2
            if (p + 2 < NPAIR) {
                const float* xc = xb + (size_t)(2 * (p + 2)) * XCH;
#pragma unroll
                for (int j = 0; j < 9; ++j) {
                    t9a[j] = (offv[j] >= 0) ? xc[offv[j]] : 0.0f;
                    t9b[j] = (offv[j] >= 0) ? xc[XCH + offv[j]] : 0.0f;
                }
            }

            asm volatile("cp.async.wait_group 0;" ::: "memory");
            __syncthreads();
        }
    }

    // ---- epilogue: direct register -> global float2 stores ----
    const int l4 = lane >> 2;
    const int l2 = (lane & 3) * 2;
#pragma unroll
    for (int mt = 0; mt < 4; ++mt) {
#pragma unroll
        for (int nt = 0; nt < 8; ++nt) {
            int oc = m0 + 16 * mt + l4;
            int pp = n0 + 8 * nt + l2;
            int hh = h0 + (pp >> 5);
            int ww = w0 + (pp & 31);
            float* p0 = out + (((size_t)(bb * NOC + oc) * IH + hh) * IW + ww);
            *(float2*)p0 = make_float2(acc[mt][nt][0], acc[mt][nt][1]);
            *(float2*)(p0 + (size_t)8 * IH * IW) =
                make_float2(acc[mt][nt][2], acc[mt][nt][3]);  // oc + 8
        }
    }
}

extern "C" void kernel_launch(void* const* d_in, const int* in_sizes, int n_in,
                              void* d_out, int out_size) {
    const float* x = (const float*)d_in[0];  // [8, 64, 96, 96]
    const float* w = (const float*)d_in[1];  // [128, 64, 54, 1]
    float* out = (float*)d_out;              // [8, 128, 96, 96]
    (void)in_sizes; (void)n_in; (void)out_size;

    cudaFuncSetAttribute(soc_fp16_kernel,
                         cudaFuncAttributeMaxDynamicSharedMemorySize, SM_TOTAL);

    prep_w<<<(NPAIR * NOC * WROW + 255) / 256, 256>>>(w);
    soc_fp16_kernel<<<NB * TILES_PER_IMG, 256, SM_TOTAL>>>(x, out);
}